// round 2
// baseline (speedup 1.0000x reference)
#include <cuda_runtime.h>
#include <math.h>

// Problem constants
#define T_  32
#define N_  64
#define C_  64
#define L_  64
#define H_  256
#define NA_ 16
#define G3_ 768     // 3*H
#define NCH 2048    // T_*N_ chains per direction

// ---------------------------------------------------------------------------
// Device scratch (static __device__ arrays: allowed; no runtime allocation)
// ---------------------------------------------------------------------------
__device__ float g_XI [2ull * 4096 * 768];          // [dir][m*64+n][3H]  (input projections, bias folded)
__device__ float g_XF1[2048ull * 256];              // MLP hidden 1
__device__ float g_XF2[2048ull * 256];              // MLP hidden 2
__device__ float g_GI [2048ull * 768];              // precomputed cell gi (bias folded)
__device__ float g_GH [2ull * 2048 * 768];          // per-step recurrent gates (no bias)
__device__ float g_H  [2ull * 2048 * 256];          // GRU hidden state per chain
__device__ float g_K  [2048ull * 2 * 64 * 256];     // all GRU outputs: [chain][dir][step][H] (~268 MB)
__device__ float g_h2 [64ull * 256];                // decoder hidden state

// ---------------------------------------------------------------------------
// Zero init for recurrent states
// ---------------------------------------------------------------------------
__global__ void zero_kernel() {
    unsigned i = blockIdx.x * 256u + threadIdx.x;
    if (i < 2u * 2048u * 256u) g_H[i] = 0.f;
    if (i < 64u * 256u)        g_h2[i] = 0.f;
}

// ---------------------------------------------------------------------------
// Generic tiled fp32 GEMM:  C[row][col] = sum_k A[row][k] * B[col][k] (+bias, relu)
//   block tile: 32 rows x 128 cols, K in chunks of 32, 256 threads, 4x4 thread tile
// mode 0: A row = embed[lines[n][m]]   (row = m*64+n)
// mode 1: A row = concat(condition[t][n], aemb[a_prev])   (row = t*64+n, K=320)
// else  : A row = A + row*K
// ---------------------------------------------------------------------------
__global__ __launch_bounds__(256)
void gemm_k(int mode, const float* __restrict__ A, const float* __restrict__ B,
            const float* __restrict__ bias, float* __restrict__ C,
            int cols, int K, int relu,
            const int* __restrict__ lines, const float* __restrict__ embed,
            const float* __restrict__ cond, const float* __restrict__ aemb,
            const int* __restrict__ a_idx)
{
    __shared__ float As[32][36];    // [k][row]  (pad 36 -> float4-aligned rows)
    __shared__ float Bs[32][132];   // [k][col]

    const int row0 = blockIdx.x * 32;
    const int col0 = blockIdx.y * 128;
    const int tid  = threadIdx.x;
    const int tx   = tid & 31;      // col group
    const int ty   = tid >> 5;      // row group

    // A-loader mapping: 32 rows x 32 k, 4 elems/thread
    const int lr  = tid >> 3;        // 0..31 local row
    const int lk4 = (tid & 7) * 4;   // 0..28 local k
    const int grow = row0 + lr;

    const float* Arow = nullptr;
    int ap = 0;
    if (mode == 0) {
        int m = grow >> 6, n = grow & 63;
        Arow = embed + (size_t)lines[n * 64 + m] * H_;
    } else if (mode == 1) {
        int t = grow >> 6;
        ap = (t == 0) ? 0 : a_idx[grow - 64];
    } else {
        Arow = A + (size_t)grow * K;
    }

    // B-loader mapping: 128 cols x 32 k, 16 elems/thread
    const int cc  = tid >> 1;           // 0..127
    const int kk0 = (tid & 1) * 16;     // 0 or 16
    const float* Brow0 = B + (size_t)(col0 + cc) * K;

    float acc[4][4];
#pragma unroll
    for (int i = 0; i < 4; i++)
#pragma unroll
        for (int j = 0; j < 4; j++) acc[i][j] = 0.f;

    for (int k0 = 0; k0 < K; k0 += 32) {
        float4 av;
        if (mode == 1) {
            float t4[4];
#pragma unroll
            for (int i = 0; i < 4; i++) {
                int k = k0 + lk4 + i;
                t4[i] = (k < 64) ? cond[(size_t)grow * 64 + k]
                                 : aemb[(size_t)ap * 256 + (k - 64)];
            }
            av = make_float4(t4[0], t4[1], t4[2], t4[3]);
        } else {
            av = *(const float4*)(Arow + k0 + lk4);
        }
        As[lk4 + 0][lr] = av.x; As[lk4 + 1][lr] = av.y;
        As[lk4 + 2][lr] = av.z; As[lk4 + 3][lr] = av.w;

        const float* bp = Brow0 + k0 + kk0;
#pragma unroll
        for (int i = 0; i < 16; i += 4) {
            float4 bv = *(const float4*)(bp + i);
            Bs[kk0 + i + 0][cc] = bv.x; Bs[kk0 + i + 1][cc] = bv.y;
            Bs[kk0 + i + 2][cc] = bv.z; Bs[kk0 + i + 3][cc] = bv.w;
        }
        __syncthreads();

#pragma unroll
        for (int kk = 0; kk < 32; kk++) {
            float4 a = *(const float4*)&As[kk][ty * 4];
            float4 b = *(const float4*)&Bs[kk][tx * 4];
            acc[0][0] += a.x * b.x; acc[0][1] += a.x * b.y; acc[0][2] += a.x * b.z; acc[0][3] += a.x * b.w;
            acc[1][0] += a.y * b.x; acc[1][1] += a.y * b.y; acc[1][2] += a.y * b.z; acc[1][3] += a.y * b.w;
            acc[2][0] += a.z * b.x; acc[2][1] += a.z * b.y; acc[2][2] += a.z * b.z; acc[2][3] += a.z * b.w;
            acc[3][0] += a.w * b.x; acc[3][1] += a.w * b.y; acc[3][2] += a.w * b.z; acc[3][3] += a.w * b.w;
        }
        __syncthreads();
    }

#pragma unroll
    for (int i = 0; i < 4; i++) {
        int row = row0 + ty * 4 + i;
        float4 v = make_float4(acc[i][0], acc[i][1], acc[i][2], acc[i][3]);
        if (bias) {
            int c = col0 + tx * 4;
            v.x += bias[c]; v.y += bias[c + 1]; v.z += bias[c + 2]; v.w += bias[c + 3];
        }
        if (relu) {
            v.x = fmaxf(v.x, 0.f); v.y = fmaxf(v.y, 0.f);
            v.z = fmaxf(v.z, 0.f); v.w = fmaxf(v.w, 0.f);
        }
        *(float4*)(C + (size_t)row * cols + col0 + tx * 4) = v;
    }
}

// ---------------------------------------------------------------------------
// GRU pointwise update for step j, both directions (2*2048 chains x 256 dims)
// ---------------------------------------------------------------------------
__global__ __launch_bounds__(256)
void gru_update(int j, const int* __restrict__ p_idx,
                const float* __restrict__ bh_f, const float* __restrict__ bh_b)
{
    unsigned idx = blockIdx.x * 256u + threadIdx.x;   // over 2*2048*256 = 2^20
    int hh = idx & 255;
    int c  = (idx >> 8) & 2047;
    int d  = idx >> 19;
    int n  = c & 63;
    int r  = p_idx[c];
    int m  = (d == 0) ? ((j - r + 64) & 63) : ((63 - j - r + 128) & 63);

    const float* xi = g_XI + ((size_t)(d * 4096 + m * 64 + n)) * 768;
    const float* gh = g_GH + ((size_t)(d * 2048 + c)) * 768;
    const float* bh = d ? bh_b : bh_f;

    float h_old = g_H[(size_t)(d * 2048 + c) * 256 + hh];
    float gir = xi[hh],       giz = xi[256 + hh],       gin = xi[512 + hh];
    float ghr = gh[hh] + bh[hh];
    float ghz = gh[256 + hh] + bh[256 + hh];
    float ghn = gh[512 + hh] + bh[512 + hh];

    float rg = 1.f / (1.f + expf(-(gir + ghr)));
    float zg = 1.f / (1.f + expf(-(giz + ghz)));
    float ng = tanhf(gin + rg * ghn);
    float h  = (1.f - zg) * ng + zg * h_old;

    g_H[(size_t)(d * 2048 + c) * 256 + hh] = h;
    g_K[(((size_t)c * 2 + d) * 64 + j) * 256 + hh] = h;
}

// ---------------------------------------------------------------------------
// Block-cooperative matvec: y[o] = W[o][:] . x[:] (+b), 8 lanes per output row
// ---------------------------------------------------------------------------
__device__ __forceinline__ void matvec8(float* __restrict__ y,
                                        const float* __restrict__ W,
                                        const float* __restrict__ b,
                                        const float* __restrict__ x,
                                        int Nout, int K)
{
    int tid  = threadIdx.x;
    int lane = tid & 31, warp = tid >> 5;
    int s = lane & 7, og = lane >> 3;
    for (int ob = warp * 4; ob < Nout; ob += 32) {       // uniform per warp
        int o = ob + og;
        bool valid = (o < Nout);
        const float* w = W + (size_t)(valid ? o : ob) * K;
        float acc = 0.f;
        for (int k = s * 4; k < K; k += 32) {
            float4 wv = *(const float4*)(w + k);
            float4 xv = *(const float4*)(x + k);
            acc += wv.x * xv.x + wv.y * xv.y + wv.z * xv.z + wv.w * xv.w;
        }
        acc += __shfl_down_sync(0xffffffffu, acc, 4);
        acc += __shfl_down_sync(0xffffffffu, acc, 2);
        acc += __shfl_down_sync(0xffffffffu, acc, 1);
        if (s == 0 && valid) y[o] = b ? (acc + b[o]) : acc;
    }
}

// ---------------------------------------------------------------------------
// Decoder step t: GRU cell + pointer/query/critic heads + key attention + actor
// One block per batch element n (64 blocks x 256 threads)
// ---------------------------------------------------------------------------
__global__ __launch_bounds__(256)
void stepC_kernel(int t,
                  const float* __restrict__ cell_wh, const float* __restrict__ cell_bh,
                  const float* __restrict__ pointer_w, const float* __restrict__ pointer_b,
                  const float* __restrict__ query_w, const float* __restrict__ query_b,
                  const float* __restrict__ actor_w, const float* __restrict__ actor_b,
                  const float* __restrict__ critic_w, const float* __restrict__ critic_b,
                  const int* __restrict__ a_idx, const int* __restrict__ p_idx,
                  float* __restrict__ out)
{
    const int n = blockIdx.x;
    const int tid = threadIdx.x;

    __shared__ float sh_h[256];
    __shared__ float sh_gh[768];
    __shared__ float sh_q[256];
    __shared__ float sh_l[128];
    __shared__ float sh_zz[256];
    __shared__ float sh_pl[64];
    __shared__ float sh_al[16];
    __shared__ float sh_v[4];
    __shared__ float s_max, s_sum;

    sh_h[tid] = g_h2[n * 256 + tid];
    __syncthreads();

    // gh = h_prev @ cell_wh^T + cell_bh
    matvec8(sh_gh, cell_wh, cell_bh, sh_h, 768, 256);
    __syncthreads();

    // GRU update
    const float* gi = g_GI + (size_t)(t * 64 + n) * 768;
    float h_old = sh_h[tid];
    float rg = 1.f / (1.f + expf(-(gi[tid]       + sh_gh[tid])));
    float zg = 1.f / (1.f + expf(-(gi[256 + tid] + sh_gh[256 + tid])));
    float ng = tanhf(gi[512 + tid] + rg * sh_gh[512 + tid]);
    float hnew = (1.f - zg) * ng + zg * h_old;
    __syncthreads();
    sh_h[tid] = hnew;
    g_h2[n * 256 + tid] = hnew;
    __syncthreads();

    // heads
    matvec8(sh_pl, pointer_w, pointer_b, sh_h, 64, 256);
    matvec8(sh_q,  query_w,   query_b,   sh_h, 256, 256);
    matvec8(sh_v,  critic_w,  critic_b,  sh_h, 1, 256);
    __syncthreads();

    // softmax over pointer logits (64)
    if (tid < 32) {
        float m = fmaxf(sh_pl[tid], sh_pl[tid + 32]);
#pragma unroll
        for (int o = 16; o > 0; o >>= 1) m = fmaxf(m, __shfl_xor_sync(0xffffffffu, m, o));
        if (tid == 0) s_max = m;
    }
    __syncthreads();
    if (tid < 64) sh_pl[tid] = expf(sh_pl[tid] - s_max);
    __syncthreads();
    if (tid < 32) {
        float s = sh_pl[tid] + sh_pl[tid + 32];
#pragma unroll
        for (int o = 16; o > 0; o >>= 1) s += __shfl_xor_sync(0xffffffffu, s, o);
        if (tid == 0) s_sum = s;
    }

    // attention over this chain's 128 GRU output keys
    const float* Kc = g_K + ((size_t)(t * 64 + n)) * 2 * 64 * 256;  // [128][256]
    __syncthreads();
    matvec8(sh_l, Kc, nullptr, sh_q, 128, 256);
    __syncthreads();

    // zz[u] = sum_k2 l[k2] * Kc[k2][u]
    {
        float acc = 0.f;
#pragma unroll 8
        for (int k2 = 0; k2 < 128; k2++) acc += sh_l[k2] * Kc[(size_t)k2 * 256 + tid];
        sh_zz[tid] = acc;
    }
    __syncthreads();

    // actor logits + softmax (16)
    matvec8(sh_al, actor_w, actor_b, sh_zz, 16, 256);
    __syncthreads();
    if (tid < 32) {
        float v = (tid < 16) ? sh_al[tid] : -1e30f;
        float m = v;
#pragma unroll
        for (int o = 16; o > 0; o >>= 1) m = fmaxf(m, __shfl_xor_sync(0xffffffffu, m, o));
        float e = (tid < 16) ? expf(v - m) : 0.f;
        float s = e;
#pragma unroll
        for (int o = 16; o > 0; o >>= 1) s += __shfl_xor_sync(0xffffffffu, s, o);
        if (tid < 16) sh_al[tid] = e / s;
    }
    __syncthreads();

    // pack output row: [a_t, p_t, v, h(256), a_probs(16), p_probs(64)] = 339
    float* orow = out + ((size_t)(t * 64 + n)) * 339;
    if (tid == 0) {
        orow[0] = (float)a_idx[t * 64 + n];
        orow[1] = (float)p_idx[t * 64 + n];
        orow[2] = sh_v[0];
    }
    orow[3 + tid] = sh_h[tid];
    if (tid < 16) orow[259 + tid] = sh_al[tid];
    if (tid < 64) orow[275 + tid] = sh_pl[tid] / s_sum;
}

// ---------------------------------------------------------------------------
// Launch
// ---------------------------------------------------------------------------
extern "C" void kernel_launch(void* const* d_in, const int* in_sizes, int n_in,
                              void* d_out, int out_size)
{
    const float* condition = (const float*)d_in[0];
    const int*   lines     = (const int*)  d_in[1];
    const int*   a_idx     = (const int*)  d_in[2];
    const int*   p_idx     = (const int*)  d_in[3];
    const float* embed     = (const float*)d_in[4];
    const float* aemb      = (const float*)d_in[5];
    const float* gru_wi_f  = (const float*)d_in[6];
    const float* gru_wh_f  = (const float*)d_in[7];
    const float* gru_bi_f  = (const float*)d_in[8];
    const float* gru_bh_f  = (const float*)d_in[9];
    const float* gru_wi_b  = (const float*)d_in[10];
    const float* gru_wh_b  = (const float*)d_in[11];
    const float* gru_bi_b  = (const float*)d_in[12];
    const float* gru_bh_b  = (const float*)d_in[13];
    const float* f_w1      = (const float*)d_in[14];
    const float* f_b1      = (const float*)d_in[15];
    const float* f_w2      = (const float*)d_in[16];
    const float* f_b2      = (const float*)d_in[17];
    const float* cell_wi   = (const float*)d_in[18];
    const float* cell_wh   = (const float*)d_in[19];
    const float* cell_bi   = (const float*)d_in[20];
    const float* cell_bh   = (const float*)d_in[21];
    const float* critic_w  = (const float*)d_in[22];
    const float* critic_b  = (const float*)d_in[23];
    const float* pointer_w = (const float*)d_in[24];
    const float* pointer_b = (const float*)d_in[25];
    const float* actor_w   = (const float*)d_in[26];
    const float* actor_b   = (const float*)d_in[27];
    const float* query_w   = (const float*)d_in[28];
    const float* query_b   = (const float*)d_in[29];
    float* out = (float*)d_out;

    void *pXI_, *pXF1_, *pXF2_, *pGI_, *pGH_, *pH_;
    cudaGetSymbolAddress(&pXI_,  g_XI);
    cudaGetSymbolAddress(&pXF1_, g_XF1);
    cudaGetSymbolAddress(&pXF2_, g_XF2);
    cudaGetSymbolAddress(&pGI_,  g_GI);
    cudaGetSymbolAddress(&pGH_,  g_GH);
    cudaGetSymbolAddress(&pH_,   g_H);
    float* pXI  = (float*)pXI_;
    float* pXF1 = (float*)pXF1_;
    float* pXF2 = (float*)pXF2_;
    float* pGI  = (float*)pGI_;
    float* pGH  = (float*)pGH_;
    float* pH   = (float*)pH_;

    // 0) zero recurrent states
    zero_kernel<<<4096, 256>>>();

    // 1) input projections XI for both GRU directions: rows = m*64+n (4096)
    gemm_k<<<dim3(128, 6), 256>>>(0, nullptr, gru_wi_f, gru_bi_f, pXI,
                                  768, 256, 0, lines, embed, nullptr, nullptr, nullptr);
    gemm_k<<<dim3(128, 6), 256>>>(0, nullptr, gru_wi_b, gru_bi_b, pXI + 4096ull * 768,
                                  768, 256, 0, lines, embed, nullptr, nullptr, nullptr);

    // 2) decoder MLP + cell input gates, batched over all (t,n)
    gemm_k<<<dim3(64, 2), 256>>>(1, nullptr, f_w1, f_b1, pXF1,
                                 256, 320, 1, nullptr, nullptr, condition, aemb, a_idx);
    gemm_k<<<dim3(64, 2), 256>>>(2, pXF1, f_w2, f_b2, pXF2,
                                 256, 256, 1, nullptr, nullptr, nullptr, nullptr, nullptr);
    gemm_k<<<dim3(64, 6), 256>>>(2, pXF2, cell_wi, cell_bi, pGI,
                                 768, 256, 0, nullptr, nullptr, nullptr, nullptr, nullptr);

    // 3) bidirectional GRU recurrence over 64 timesteps, 2048 chains per dir
    for (int j = 0; j < 64; j++) {
        gemm_k<<<dim3(64, 6), 256>>>(2, pH, gru_wh_f, nullptr, pGH,
                                     768, 256, 0, nullptr, nullptr, nullptr, nullptr, nullptr);
        gemm_k<<<dim3(64, 6), 256>>>(2, pH + 2048ull * 256, gru_wh_b, nullptr, pGH + 2048ull * 768,
                                     768, 256, 0, nullptr, nullptr, nullptr, nullptr, nullptr);
        gru_update<<<4096, 256>>>(j, p_idx, gru_bh_f, gru_bh_b);
    }

    // 4) decoder loop over T=32 steps
    for (int t = 0; t < T_; t++) {
        stepC_kernel<<<64, 256>>>(t, cell_wh, cell_bh, pointer_w, pointer_b,
                                  query_w, query_b, actor_w, actor_b,
                                  critic_w, critic_b, a_idx, p_idx, out);
    }
}